// round 10
// baseline (speedup 1.0000x reference)
#include <cuda_runtime.h>
#include <cuda_bf16.h>
#include <cstdint>

// ---------------------------------------------------------------------------
// SPMoEAdaptor: out = moe_b(moe_a(x)) + x
//   moe(x) = sum_e softmax(x@Wg)[:,e] * ((x - b_e) @ W_e)
// R9: int8 tensor cores (mma.m16n8k32.s8 — baseline PTX, 2x K per MMA).
// Symmetric static quantization: x*32, W*1536, h*192; exact s32 accumulate
// per expert, fp32 gate-scale fold (g_e / (S_in*S_w)), bias/residual fp32.
// Halves HMMA count (528->264/unit) and LDSM (128->64/unit). smem 36KB,
// 3 CTAs/SM, work-stealing + L2 prefetch retained from R7.
// ---------------------------------------------------------------------------

namespace {
constexpr int SM_W8  = 0;               // 32KB int8 weights, both layers
constexpr int SM_WGA = 32768;           // 64x4 fp32 gate weights [d][e]
constexpr int SM_WGB = 33792;
constexpr int SM_CA  = 34816;           // c_a * 49152  (f32, [f][e])
constexpr int SM_CB  = 35840;           // c_b * 294912
constexpr int SMEM_TOTAL = 36864;       // 36KB -> 3 CTAs/SM

constexpr int GRID = 444;               // 148 SMs * 3 CTAs/SM

constexpr float SX = 32.f;              // x quant scale   (clip 3.97 sigma)
constexpr float SH = 192.f;             // h quant scale
constexpr float SW = 1536.f;            // weight quant scale (clip 4.1 sigma)
constexpr float INV_XW = 1.f / (32.f * 1536.f);    // 1/49152
constexpr float INV_HW = 1.f / (192.f * 1536.f);   // 1/294912
}

// device-global scratch (allocation-free rule)
// int8 weight image: [L][e][nb][kc][kh][n(8)][16 bytes], 512B per (e,nb)
__device__ __align__(16) signed char g_w8[2][16384];
__device__ __align__(16) float g_c[2][256];      // pre-scaled bias correction
__device__ unsigned g_unit_ctr;                  // work-stealing counter

// ------------------------------- helpers ----------------------------------

__device__ __forceinline__ uint32_t smem_u32(const void* p) {
    uint32_t a;
    asm("{ .reg .u64 t; cvta.to.shared.u64 t, %1; cvt.u32.u64 %0, t; }" : "=r"(a) : "l"(p));
    return a;
}

__device__ __forceinline__ void ldsm_x4(uint32_t* r, uint32_t addr) {
    asm volatile("ldmatrix.sync.aligned.m8n8.x4.shared.b16 {%0,%1,%2,%3}, [%4];"
                 : "=r"(r[0]), "=r"(r[1]), "=r"(r[2]), "=r"(r[3]) : "r"(addr));
}

// d = A*B + z   (z = persistent zeros; d written fresh)
__device__ __forceinline__ void mma_s8_cz(int* d, const uint32_t* a,
                                          uint32_t b0, uint32_t b1, const int* z) {
    asm volatile("mma.sync.aligned.m16n8k32.row.col.s32.s8.s8.s32 "
                 "{%0,%1,%2,%3}, {%4,%5,%6,%7}, {%8,%9}, {%10,%11,%12,%13};"
                 : "=r"(d[0]), "=r"(d[1]), "=r"(d[2]), "=r"(d[3])
                 : "r"(a[0]), "r"(a[1]), "r"(a[2]), "r"(a[3]), "r"(b0), "r"(b1),
                   "r"(z[0]), "r"(z[1]), "r"(z[2]), "r"(z[3]));
}

// d += A*B
__device__ __forceinline__ void mma_s8_acc(int* d, const uint32_t* a,
                                           uint32_t b0, uint32_t b1) {
    asm volatile("mma.sync.aligned.m16n8k32.row.col.s32.s8.s8.s32 "
                 "{%0,%1,%2,%3}, {%4,%5,%6,%7}, {%8,%9}, {%0,%1,%2,%3};"
                 : "+r"(d[0]), "+r"(d[1]), "+r"(d[2]), "+r"(d[3])
                 : "r"(a[0]), "r"(a[1]), "r"(a[2]), "r"(a[3]), "r"(b0), "r"(b1));
}

__device__ __forceinline__ int cvt_s8(float v) {
    int r;
    asm("cvt.rni.sat.s8.f32 %0, %1;" : "=r"(r) : "f"(v));
    return r;
}

__device__ __forceinline__ uint32_t prmt(uint32_t a, uint32_t b, uint32_t sel) {
    uint32_t r;
    asm("prmt.b32 %0, %1, %2, %3;" : "=r"(r) : "r"(a), "r"(b), "r"(sel));
    return r;
}

// 4 floats * s -> packed s8x4
__device__ __forceinline__ uint32_t q4(float4 v, float s) {
    uint32_t i0 = (uint32_t)cvt_s8(v.x * s);
    uint32_t i1 = (uint32_t)cvt_s8(v.y * s);
    uint32_t i2 = (uint32_t)cvt_s8(v.z * s);
    uint32_t i3 = (uint32_t)cvt_s8(v.w * s);
    return prmt(prmt(i0, i1, 0x0040u), prmt(i2, i3, 0x0040u), 0x5410u);
}

__device__ __forceinline__ float comp4(float4 v, int e) {
    return e == 0 ? v.x : e == 1 ? v.y : e == 2 ? v.z : v.w;
}

__device__ __forceinline__ float dot4(float4 a, float4 b) {
    return a.x * b.x + a.y * b.y + a.z * b.z + a.w * b.w;
}

__device__ __forceinline__ float4 softmax4(float4 l) {
    float mx = fmaxf(fmaxf(l.x, l.y), fmaxf(l.z, l.w));
    float e0 = __expf(l.x - mx), e1 = __expf(l.y - mx),
          e2 = __expf(l.z - mx), e3 = __expf(l.w - mx);
    float inv = 1.f / (e0 + e1 + e2 + e3);
    return make_float4(e0 * inv, e1 * inv, e2 * inv, e3 * inv);
}

__device__ __forceinline__ unsigned steal(int lane) {
    unsigned v = 0;
    if (lane == 0) v = atomicAdd(&g_unit_ctr, 1u);
    return __shfl_sync(0xffffffffu, v, 0);
}

// gates for one m: logits via 2 int8 MMAs, quad gather, softmax, pre-scaled
// by fscale (so outputs double as fold factors and dot with pre-scaled c).
__device__ __forceinline__ void gates_i8(const uint32_t afm[2][4],
                                         const uint32_t* wg, float inv,
                                         float fscale, int ql, const int* z,
                                         float4 out[2]) {
    int t[4];
    mma_s8_cz(t, afm[0], wg[0], wg[1], z);
    mma_s8_acc(t, afm[1], wg[2], wg[3]);
    float l0 = (float)t[0] * inv, l1 = (float)t[1] * inv;
    float l2 = (float)t[2] * inv, l3 = (float)t[3] * inv;
    float r0 = __shfl_xor_sync(0xffffffffu, l0, 1);
    float r1 = __shfl_xor_sync(0xffffffffu, l1, 1);
    float r2 = __shfl_xor_sync(0xffffffffu, l2, 1);
    float r3 = __shfl_xor_sync(0xffffffffu, l3, 1);
    bool even = (ql & 1) == 0;
    float4 La = even ? make_float4(l0, l1, r0, r1) : make_float4(r0, r1, l0, l1);
    float4 Lb = even ? make_float4(l2, l3, r2, r3) : make_float4(r2, r3, l2, l3);
    float4 ga = softmax4(La);
    float4 gb = softmax4(Lb);
    out[0] = make_float4(ga.x * fscale, ga.y * fscale, ga.z * fscale, ga.w * fscale);
    out[1] = make_float4(gb.x * fscale, gb.y * fscale, gb.z * fscale, gb.w * fscale);
}

// one MoE GEMM layer in int8: per (e,nb): one ldsm.x4 gives B for both
// k-chunks; per m: 2-MMA s32 chain; fp32 fold acc += f[m][rh][e]*t.
__device__ __forceinline__ void run_layer_i8(float acc[2][8][4],
                                             const uint32_t af[2][2][4],
                                             const float4 ff[2][2],
                                             uint32_t wbase, int lane,
                                             const int* z) {
    const uint32_t labase = wbase + (uint32_t)lane * 16u;
    #pragma unroll
    for (int e = 0; e < 4; e++) {
        #pragma unroll
        for (int nb = 0; nb < 8; nb++) {
            uint32_t b[4];
            ldsm_x4(b, labase + (uint32_t)(e * 8 + nb) * 512u);
            #pragma unroll
            for (int m = 0; m < 2; m++) {
                int t[4];
                mma_s8_cz(t, af[m][0], b[0], b[1], z);
                mma_s8_acc(t, af[m][1], b[2], b[3]);
                float f0 = comp4(ff[m][0], e);
                float f1 = comp4(ff[m][1], e);
                acc[m][nb][0] = fmaf(f0, (float)t[0], acc[m][nb][0]);
                acc[m][nb][1] = fmaf(f0, (float)t[1], acc[m][nb][1]);
                acc[m][nb][2] = fmaf(f1, (float)t[2], acc[m][nb][2]);
                acc[m][nb][3] = fmaf(f1, (float)t[3], acc[m][nb][3]);
            }
        }
    }
}

// ------------------------------- prep kernel ------------------------------

__global__ void prep_kernel(const float* __restrict__ wea, const float* __restrict__ bea,
                            const float* __restrict__ web, const float* __restrict__ beb) {
    int idx = blockIdx.x * blockDim.x + threadIdx.x;
    if (idx == 0) g_unit_ctr = 0;
    if (idx < 2 * 4 * 64 * 64) {
        int L = idx >> 14;
        int r = idx & 16383;
        int e = r >> 12;
        int d = (r >> 6) & 63;
        int f = r & 63;
        const float* w = L ? web : wea;
        float v = w[(e * 64 + d) * 64 + f] * SW;
        int q = __float2int_rn(v);
        q = q > 127 ? 127 : (q < -128 ? -128 : q);
        // [e][nb=f>>3][kc=d>>5][kh=(d>>4)&1][n=f&7][byte=d&15]
        int off = ((e * 8 + (f >> 3)) * 4 + ((d >> 5) << 1) + ((d >> 4) & 1)) * 128
                + (f & 7) * 16 + (d & 15);
        g_w8[L][off] = (signed char)q;
    }
    if (idx < 2 * 4 * 64) {
        int L = idx >> 8;
        int e = (idx >> 6) & 3;
        int f = idx & 63;
        const float* w = L ? web : wea;
        const float* b = L ? beb : bea;
        float s = 0.f;
        for (int d = 0; d < 64; d++)
            s += b[e * 64 + d] * w[(e * 64 + d) * 64 + f];
        g_c[L][f * 4 + e] = s * (L ? (SH * SW) : (SX * SW));
    }
}

// ------------------------------- main kernel ------------------------------

__global__ void __launch_bounds__(128, 3)
moe_kernel(const float* __restrict__ x,
           const float* __restrict__ wg_a,
           const float* __restrict__ wg_b,
           float* __restrict__ out,
           int nunits_i) {
    extern __shared__ char smem[];
    const uint32_t sb = smem_u32(smem);
    const int tid  = threadIdx.x;
    const int lane = tid & 31;
    const unsigned nunits = (unsigned)nunits_i;

    // ---- one-time cooperative weight copies ----
    {
        const uint4* s8 = reinterpret_cast<const uint4*>(g_w8);
        uint4* d8 = reinterpret_cast<uint4*>(smem + SM_W8);
        #pragma unroll
        for (int i = tid; i < 2048; i += 128) d8[i] = s8[i];
        float* wga_s = reinterpret_cast<float*>(smem + SM_WGA);
        float* wgb_s = reinterpret_cast<float*>(smem + SM_WGB);
        float* ca_s  = reinterpret_cast<float*>(smem + SM_CA);
        float* cb_s  = reinterpret_cast<float*>(smem + SM_CB);
        #pragma unroll
        for (int i = tid; i < 256; i += 128) {
            wga_s[i] = wg_a[i]; wgb_s[i] = wg_b[i];
            ca_s[i]  = g_c[0][i]; cb_s[i] = g_c[1][i];
        }
    }
    __syncthreads();

    const float4* CA4 = reinterpret_cast<const float4*>(smem + SM_CA);
    const float4* CB4 = reinterpret_cast<const float4*>(smem + SM_CB);

    const int ql = lane & 3;
    const int qr = lane >> 2;
    const int z4[4] = {0, 0, 0, 0};

    // ---- gate weight int8 B-fragments (tile-invariant, x16 regs -> 8) ----
    uint32_t wgA[4], wgB[4];
    {
        const float* WGAf = reinterpret_cast<const float*>(smem + SM_WGA);
        const float* WGBf = reinterpret_cast<const float*>(smem + SM_WGB);
        const int e4 = qr & 3;
        #pragma unroll
        for (int kc = 0; kc < 2; kc++)
            #pragma unroll
            for (int kh = 0; kh < 2; kh++) {
                int d0 = 32 * kc + 16 * kh + 4 * ql;
                float4 v = make_float4(WGAf[(d0 + 0) * 4 + e4], WGAf[(d0 + 1) * 4 + e4],
                                       WGAf[(d0 + 2) * 4 + e4], WGAf[(d0 + 3) * 4 + e4]);
                wgA[kc * 2 + kh] = q4(v, SW);
                float4 u = make_float4(WGBf[(d0 + 0) * 4 + e4], WGBf[(d0 + 1) * 4 + e4],
                                       WGBf[(d0 + 2) * 4 + e4], WGBf[(d0 + 3) * 4 + e4]);
                wgB[kc * 2 + kh] = q4(u, SW);
            }
    }

    const uint32_t wbaseA = sb + SM_W8;
    const uint32_t wbaseB = sb + SM_W8 + 16384;
    const uint32_t qh = (uint32_t)(ql >> 1);
    const uint32_t dsel = qh ? 0x7632u : 0x5410u;
    const int L0 = 2 * (ql & 1);

    unsigned u = steal(lane);
    while (u < nunits) {
        unsigned un = steal(lane);     // pipelined next-unit fetch
        const size_t rowbase = (size_t)u * 32;

        // ---- x loads (float4 at 4ql: matches s8 A-frag layout) + quant ----
        uint32_t af[2][2][4];
        #pragma unroll
        for (int m = 0; m < 2; m++) {
            const size_t r = rowbase + (size_t)(m * 16 + qr);
            const float* x0 = x + r * 64 + 4 * ql;
            const float* x8 = x0 + 8 * 64;
            #pragma unroll
            for (int kc = 0; kc < 2; kc++) {
                float4 g0 = *reinterpret_cast<const float4*>(x0 + 32 * kc);
                float4 h0 = *reinterpret_cast<const float4*>(x8 + 32 * kc);
                float4 g1 = *reinterpret_cast<const float4*>(x0 + 32 * kc + 16);
                float4 h1 = *reinterpret_cast<const float4*>(x8 + 32 * kc + 16);
                af[m][kc][0] = q4(g0, SX);
                af[m][kc][1] = q4(h0, SX);
                af[m][kc][2] = q4(g1, SX);
                af[m][kc][3] = q4(h1, SX);
            }
        }

        // ---- prefetch next unit's x into L2 ----
        if (un < nunits) {
            const char* p = reinterpret_cast<const char*>(x + (size_t)un * 32 * 64)
                          + lane * 256;
            asm volatile("prefetch.global.L2 [%0];" :: "l"(p));
            asm volatile("prefetch.global.L2 [%0];" :: "l"(p + 128));
        }

        // ---- gates A (pre-scaled by 1/(Sx*Sw): fold factors + bias dots) --
        float4 fA[2][2];
        #pragma unroll
        for (int m = 0; m < 2; m++)
            gates_i8(af[m], wgA, INV_XW, INV_XW, ql, z4, fA[m]);

        // ---- layer A: acc init = -sum_e g_e c_a, then int8 GEMM ----
        float acc[2][8][4];
        #pragma unroll
        for (int n = 0; n < 8; n++) {
            int c = n * 8 + ql * 2;
            float4 c0 = CA4[c], c1 = CA4[c + 1];
            #pragma unroll
            for (int m = 0; m < 2; m++) {
                acc[m][n][0] = -dot4(fA[m][0], c0);
                acc[m][n][1] = -dot4(fA[m][0], c1);
                acc[m][n][2] = -dot4(fA[m][1], c0);
                acc[m][n][3] = -dot4(fA[m][1], c1);
            }
        }
        run_layer_i8(acc, af, fA, wbaseA, lane, z4);

        // ---- repack h -> int8 A-frags (quad byte shuffle) ----
        #pragma unroll
        for (int m = 0; m < 2; m++)
            #pragma unroll
            for (int rh = 0; rh < 2; rh++) {
                uint32_t p8[8];
                #pragma unroll
                for (int n = 0; n < 8; n++) {
                    uint32_t i0 = (uint32_t)cvt_s8(acc[m][n][2 * rh] * SH);
                    uint32_t i1 = (uint32_t)cvt_s8(acc[m][n][2 * rh + 1] * SH);
                    p8[n] = prmt(i0, i1, 0x0040u);
                }
                uint32_t v0 = prmt(p8[0], p8[1], 0x5410u);
                uint32_t v1 = prmt(p8[2], p8[3], 0x5410u);
                uint32_t v2 = prmt(p8[4], p8[5], 0x5410u);
                uint32_t v3 = prmt(p8[6], p8[7], 0x5410u);
                uint32_t w00 = __shfl_sync(0xffffffffu, v0, L0, 4);
                uint32_t w01 = __shfl_sync(0xffffffffu, v1, L0, 4);
                uint32_t w02 = __shfl_sync(0xffffffffu, v2, L0, 4);
                uint32_t w03 = __shfl_sync(0xffffffffu, v3, L0, 4);
                uint32_t w10 = __shfl_sync(0xffffffffu, v0, L0 + 1, 4);
                uint32_t w11 = __shfl_sync(0xffffffffu, v1, L0 + 1, 4);
                uint32_t w12 = __shfl_sync(0xffffffffu, v2, L0 + 1, 4);
                uint32_t w13 = __shfl_sync(0xffffffffu, v3, L0 + 1, 4);
                af[m][0][0 + rh] = prmt(w00, w10, dsel);   // kc0,s0
                af[m][0][2 + rh] = prmt(w01, w11, dsel);   // kc0,s1
                af[m][1][0 + rh] = prmt(w02, w12, dsel);   // kc1,s0
                af[m][1][2 + rh] = prmt(w03, w13, dsel);   // kc1,s1
            }

        // ---- gates B ----
        float4 fB[2][2];
        #pragma unroll
        for (int m = 0; m < 2; m++)
            gates_i8(af[m], wgB, INV_HW, INV_HW, ql, z4, fB[m]);

        // ---- layer B: acc init = x (residual) - sum_e g_e c_b, then GEMM --
        #pragma unroll
        for (int n = 0; n < 8; n++) {
            int c = n * 8 + ql * 2;
            float4 c0 = CB4[c], c1 = CB4[c + 1];
            #pragma unroll
            for (int m = 0; m < 2; m++) {
                const size_t rl = rowbase + (size_t)(m * 16 + qr);
                const size_t rh8 = rl + 8;
                float2 xl = *reinterpret_cast<const float2*>(x + rl * 64 + c);
                float2 xh = *reinterpret_cast<const float2*>(x + rh8 * 64 + c);
                acc[m][n][0] = xl.x - dot4(fB[m][0], c0);
                acc[m][n][1] = xl.y - dot4(fB[m][0], c1);
                acc[m][n][2] = xh.x - dot4(fB[m][1], c0);
                acc[m][n][3] = xh.y - dot4(fB[m][1], c1);
            }
        }
        run_layer_i8(acc, af, fB, wbaseB, lane, z4);

        // ---- epilogue: pure streaming stores ----
        #pragma unroll
        for (int m = 0; m < 2; m++) {
            const size_t rl = rowbase + (size_t)(m * 16 + qr);
            const size_t rh8 = rl + 8;
            #pragma unroll
            for (int n = 0; n < 8; n++) {
                int c = n * 8 + ql * 2;
                __stcs(reinterpret_cast<float2*>(out + rl * 64 + c),
                       make_float2(acc[m][n][0], acc[m][n][1]));
                __stcs(reinterpret_cast<float2*>(out + rh8 * 64 + c),
                       make_float2(acc[m][n][2], acc[m][n][3]));
            }
        }

        u = un;
    }
}

// ------------------------------- launch -----------------------------------

extern "C" void kernel_launch(void* const* d_in, const int* in_sizes, int n_in,
                              void* d_out, int out_size) {
    const float* x   = (const float*)d_in[0];
    const float* wga = (const float*)d_in[1];
    const float* wea = (const float*)d_in[2];
    const float* bea = (const float*)d_in[3];
    const float* wgb = (const float*)d_in[4];
    const float* web = (const float*)d_in[5];
    const float* beb = (const float*)d_in[6];
    float* out = (float*)d_out;

    const int ntok   = in_sizes[0] / 64;
    const int nunits = ntok / 32;

    prep_kernel<<<64, 512>>>(wea, bea, web, beb);

    cudaFuncSetAttribute(moe_kernel, cudaFuncAttributeMaxDynamicSharedMemorySize, SMEM_TOTAL);
    moe_kernel<<<GRID, 128, SMEM_TOTAL>>>(x, wga, wgb, out, nunits);
}

// round 11
// speedup vs baseline: 2.4662x; 2.4662x over previous
#include <cuda_runtime.h>
#include <cuda_bf16.h>
#include <cstdint>

// ---------------------------------------------------------------------------
// SPMoEAdaptor: out = moe_b(moe_a(x)) + x
//   moe(x) = sum_e softmax(x@Wg)[:,e] * ((x - b_e) @ W_e)
//          = sum_e (g_e * x) @ W_e  -  sum_e g_e * (b_e @ W_e)
// R10: R7 math (bf16 HMMA — the only fast legacy-MMA path on sm_103; int8
// measured rt~50cyc, reverted) + cp.async smem staging of x. One 384-thread
// CTA/SM (12 warps, same 168-reg cap as R7's 3x128) unlocks 227KB smem: each
// warp owns a 9KB x-stage (288B row stride, conflict-free for both read
// patterns) filled for unit u+1 while unit u's layer-B MMAs drain. Unit-top
// x reads become LDS (~29cyc) instead of DRAM/L2 LDG. Work-stealing kept.
// ---------------------------------------------------------------------------

namespace {
// dynamic smem layout (bytes)
constexpr int SM_W    = 0;              // 64KB bf16 weights, both layers (n-major)
constexpr int SM_WGA  = 65536;          // 64 x float4 (w_gate_a as [d][e])
constexpr int SM_WGB  = 66560;
constexpr int SM_CA   = 67584;          // 64 x float4 (c_a as [f][e])
constexpr int SM_CB   = 68608;
constexpr int SM_STAGE = 69632;         // 12 warps x 9216B x-stage
constexpr int STAGE_ROW  = 288;         // 256B data + 32B pad (bank-conflict-free)
constexpr int STAGE_WARP = 32 * STAGE_ROW;   // 9216
constexpr int SMEM_TOTAL = SM_STAGE + 12 * STAGE_WARP;  // 180224

constexpr int GRID = 148;               // 1 CTA per SM
}

// device-global scratch (allocation-free rule)
// n-major: row f (0..63), 256 bf16 per row (k = e*64+d), chunk-XOR swizzled.
__device__ __align__(16) __nv_bfloat16 g_wswz[2][64 * 256];
__device__ __align__(16) float g_c[2][64 * 4];   // c[L][f*4+e] = (b_e @ W_e)[f]
__device__ unsigned g_unit_ctr;                  // work-stealing counter

// ------------------------------- helpers ----------------------------------

__device__ __forceinline__ uint32_t smem_u32(const void* p) {
    uint32_t a;
    asm("{ .reg .u64 t; cvta.to.shared.u64 t, %1; cvt.u32.u64 %0, t; }" : "=r"(a) : "l"(p));
    return a;
}

__device__ __forceinline__ void ldsm_x4(uint32_t* r, uint32_t addr) {
    asm volatile("ldmatrix.sync.aligned.m8n8.x4.shared.b16 {%0,%1,%2,%3}, [%4];"
                 : "=r"(r[0]), "=r"(r[1]), "=r"(r[2]), "=r"(r[3]) : "r"(addr));
}

__device__ __forceinline__ void mma_bf16(float* d, const uint32_t* a,
                                         uint32_t b0, uint32_t b1) {
    asm volatile("mma.sync.aligned.m16n8k16.row.col.f32.bf16.bf16.f32 "
                 "{%0,%1,%2,%3}, {%4,%5,%6,%7}, {%8,%9}, {%0,%1,%2,%3};"
                 : "+f"(d[0]), "+f"(d[1]), "+f"(d[2]), "+f"(d[3])
                 : "r"(a[0]), "r"(a[1]), "r"(a[2]), "r"(a[3]), "r"(b0), "r"(b1));
}

__device__ __forceinline__ uint32_t pack_bf2(float lo, float hi) {
    __nv_bfloat162 t = __floats2bfloat162_rn(lo, hi);
    return *reinterpret_cast<uint32_t*>(&t);
}

__device__ __forceinline__ uint32_t bf2bcast(float v) { return pack_bf2(v, v); }

__device__ __forceinline__ uint32_t hmul2u(uint32_t a, uint32_t b) {
    __nv_bfloat162 r = __hmul2(*reinterpret_cast<__nv_bfloat162*>(&a),
                               *reinterpret_cast<__nv_bfloat162*>(&b));
    return *reinterpret_cast<uint32_t*>(&r);
}

__device__ __forceinline__ float dot4(float4 a, float4 b) {
    return a.x * b.x + a.y * b.y + a.z * b.z + a.w * b.w;
}

__device__ __forceinline__ float4 softmax4(float4 l) {
    float mx = fmaxf(fmaxf(l.x, l.y), fmaxf(l.z, l.w));
    float e0 = __expf(l.x - mx), e1 = __expf(l.y - mx),
          e2 = __expf(l.z - mx), e3 = __expf(l.w - mx);
    float inv = 1.f / (e0 + e1 + e2 + e3);
    return make_float4(e0 * inv, e1 * inv, e2 * inv, e3 * inv);
}

__device__ __forceinline__ unsigned steal(int lane) {
    unsigned v = 0;
    if (lane == 0) v = atomicAdd(&g_unit_ctr, 1u);
    return __shfl_sync(0xffffffffu, v, 0);
}

// issue cp.async copies of unit u's 32x64 fp32 x-rows into this warp's stage
__device__ __forceinline__ void issue_stage(const float* __restrict__ x, unsigned u,
                                            uint32_t dstbase, int lane) {
    const float* src = x + (size_t)u * 32 * 64;
    const int hl = lane >> 4;      // 0/1
    const int ch = lane & 15;      // 16B chunk within row
    #pragma unroll
    for (int i = 0; i < 16; i++) {
        int row = 2 * i + hl;
        uint32_t dst = dstbase + (uint32_t)(row * STAGE_ROW + ch * 16);
        const float* s = src + row * 64 + ch * 4;
        asm volatile("cp.async.cg.shared.global [%0], [%1], 16;" :: "r"(dst), "l"(s));
    }
    asm volatile("cp.async.commit_group;" ::: "memory");
}

__device__ __forceinline__ void stage_wait() {
    asm volatile("cp.async.wait_group 0;" ::: "memory");
    __syncwarp();
}

// one MoE GEMM layer: acc[2][8][4] += sum over e,kt of (g_e o A_frag) @ W_frag
// Weights n-major; ldsm.x4 (non-trans) yields mma.row.col B-fragments directly.
__device__ __forceinline__ void run_layer(float acc[2][8][4],
                                          const uint32_t xf[2][4][4],
                                          const uint32_t g2[4][2][2],
                                          uint32_t wbase, int lane) {
    const int l7 = lane & 7;
    const uint32_t lane_row = (uint32_t)(((lane >> 4) & 1) * 8 + l7);
    const uint32_t kh = (uint32_t)((lane >> 3) & 1);
    const uint32_t lane_base = wbase + lane_row * 512u;
    #pragma unroll
    for (int e = 0; e < 4; e++) {
        #pragma unroll
        for (int kt = 0; kt < 4; kt++) {
            uint32_t a[2][4];
            #pragma unroll
            for (int m = 0; m < 2; m++) {
                a[m][0] = hmul2u(xf[m][kt][0], g2[e][m][0]);
                a[m][1] = hmul2u(xf[m][kt][1], g2[e][m][1]);
                a[m][2] = hmul2u(xf[m][kt][2], g2[e][m][0]);
                a[m][3] = hmul2u(xf[m][kt][3], g2[e][m][1]);
            }
            const uint32_t c0 = (uint32_t)(e * 8 + kt * 2) + kh;
            const uint32_t coff = ((c0 ^ (uint32_t)l7) << 4);
            #pragma unroll
            for (int np = 0; np < 4; np++) {
                uint32_t b[4];
                ldsm_x4(b, lane_base + (uint32_t)np * 8192u + coff);
                #pragma unroll
                for (int m = 0; m < 2; m++) {
                    mma_bf16(acc[m][2 * np],     a[m], b[0], b[1]);
                    mma_bf16(acc[m][2 * np + 1], a[m], b[2], b[3]);
                }
            }
        }
    }
}

// gates from A-fragments via tensor core (cols 4..7 duplicate experts 0..3;
// one shfl_xor(1) completes the gather). Two accumulator chains.
__device__ __forceinline__ void gates_from_frags(const uint32_t xf[4][4],
                                                 const uint32_t* wg0,
                                                 const uint32_t* wg1,
                                                 int ql,
                                                 float4 gf[2],
                                                 uint32_t g2[4][2]) {
    float l[4]  = {0.f, 0.f, 0.f, 0.f};
    float l2[4] = {0.f, 0.f, 0.f, 0.f};
    mma_bf16(l,  xf[0], wg0[0], wg1[0]);
    mma_bf16(l2, xf[1], wg0[1], wg1[1]);
    mma_bf16(l,  xf[2], wg0[2], wg1[2]);
    mma_bf16(l2, xf[3], wg0[3], wg1[3]);
    l[0] += l2[0]; l[1] += l2[1]; l[2] += l2[2]; l[3] += l2[3];
    float r0 = __shfl_xor_sync(0xffffffffu, l[0], 1);
    float r1 = __shfl_xor_sync(0xffffffffu, l[1], 1);
    float r2 = __shfl_xor_sync(0xffffffffu, l[2], 1);
    float r3 = __shfl_xor_sync(0xffffffffu, l[3], 1);
    bool even = (ql & 1) == 0;
    float4 La = even ? make_float4(l[0], l[1], r0, r1)
                     : make_float4(r0, r1, l[0], l[1]);
    float4 Lb = even ? make_float4(l[2], l[3], r2, r3)
                     : make_float4(r2, r3, l[2], l[3]);
    float4 ga = softmax4(La);
    float4 gb = softmax4(Lb);
    gf[0] = ga; gf[1] = gb;
    g2[0][0] = bf2bcast(ga.x); g2[1][0] = bf2bcast(ga.y);
    g2[2][0] = bf2bcast(ga.z); g2[3][0] = bf2bcast(ga.w);
    g2[0][1] = bf2bcast(gb.x); g2[1][1] = bf2bcast(gb.y);
    g2[2][1] = bf2bcast(gb.z); g2[3][1] = bf2bcast(gb.w);
}

// ------------------------------- prep kernel ------------------------------

__global__ void prep_kernel(const float* __restrict__ wea, const float* __restrict__ bea,
                            const float* __restrict__ web, const float* __restrict__ beb) {
    int idx = blockIdx.x * blockDim.x + threadIdx.x;
    if (idx == 0) g_unit_ctr = 0;
    if (idx < 2 * 4 * 64 * 64) {
        int L = idx >> 14;
        int r = idx & 16383;
        int e = r >> 12;
        int d = (r >> 6) & 63;
        int f = r & 63;
        const float* w = L ? web : wea;
        float v = w[(e * 64 + d) * 64 + f];
        int chunk = (e * 8 + (d >> 3)) ^ (f & 7);
        g_wswz[L][f * 256 + chunk * 8 + (d & 7)] = __float2bfloat16(v);
    }
    if (idx < 2 * 4 * 64) {
        int L = idx >> 8;
        int e = (idx >> 6) & 3;
        int f = idx & 63;
        const float* w = L ? web : wea;
        const float* b = L ? beb : bea;
        float s = 0.f;
        for (int d = 0; d < 64; d++)
            s += b[e * 64 + d] * w[(e * 64 + d) * 64 + f];
        g_c[L][f * 4 + e] = s;
    }
}

// ------------------------------- main kernel ------------------------------

__global__ void __launch_bounds__(384, 1)
moe_kernel(const float* __restrict__ x,
           const float* __restrict__ wg_a,
           const float* __restrict__ wg_b,
           float* __restrict__ out,
           int nunits_i) {
    extern __shared__ char smem[];
    const uint32_t sb = smem_u32(smem);
    const int tid  = threadIdx.x;
    const int lane = tid & 31;
    const int warp = tid >> 5;          // 0..11
    const unsigned nunits = (unsigned)nunits_i;

    // ---- one-time cooperative weight copies ----
    {
        const uint4* s0 = reinterpret_cast<const uint4*>(g_wswz);
        uint4* dW = reinterpret_cast<uint4*>(smem + SM_W);
        for (int i = tid; i < 4096; i += 384) dW[i] = s0[i];
        float* wga_s = reinterpret_cast<float*>(smem + SM_WGA);
        float* wgb_s = reinterpret_cast<float*>(smem + SM_WGB);
        float* ca_s  = reinterpret_cast<float*>(smem + SM_CA);
        float* cb_s  = reinterpret_cast<float*>(smem + SM_CB);
        if (tid < 256) {
            wga_s[tid] = wg_a[tid]; wgb_s[tid] = wg_b[tid];
            ca_s[tid]  = g_c[0][tid]; cb_s[tid] = g_c[1][tid];
        }
    }
    __syncthreads();

    const float4* CA4 = reinterpret_cast<const float4*>(smem + SM_CA);
    const float4* CB4 = reinterpret_cast<const float4*>(smem + SM_CB);

    const int ql = lane & 3;
    const int qr = lane >> 2;
    const char* stage = smem + SM_STAGE + warp * STAGE_WARP;
    const uint32_t stage_u32 = sb + (uint32_t)(SM_STAGE + warp * STAGE_WARP);

    // ---- register-resident Wg B-fragments (tile-invariant) ----
    uint32_t wgA0[4], wgA1[4], wgB0[4], wgB1[4];
    {
        const float* WGAf = reinterpret_cast<const float*>(smem + SM_WGA);
        const float* WGBf = reinterpret_cast<const float*>(smem + SM_WGB);
        const int e4 = qr & 3;
        #pragma unroll
        for (int kt = 0; kt < 4; kt++) {
            int d0 = kt * 16 + 2 * ql;
            wgA0[kt] = pack_bf2(WGAf[d0 * 4 + e4],       WGAf[(d0 + 1) * 4 + e4]);
            wgA1[kt] = pack_bf2(WGAf[(d0 + 8) * 4 + e4], WGAf[(d0 + 9) * 4 + e4]);
            wgB0[kt] = pack_bf2(WGBf[d0 * 4 + e4],       WGBf[(d0 + 1) * 4 + e4]);
            wgB1[kt] = pack_bf2(WGBf[(d0 + 8) * 4 + e4], WGBf[(d0 + 9) * 4 + e4]);
        }
    }

    // ---- work-stealing loop with cp.async staged x ----
    unsigned u = steal(lane);
    if (u < nunits) issue_stage(x, u, stage_u32, lane);

    while (u < nunits) {
        unsigned un = steal(lane);      // pipelined next-unit fetch
        const size_t rowbase = (size_t)u * 32;

        stage_wait();                   // x for unit u ready in smem

        // ---- X fragments from stage (LDS) ----
        uint32_t xf[2][4][4];
        #pragma unroll
        for (int m = 0; m < 2; m++) {
            const char* r0p = stage + (m * 16 + qr) * STAGE_ROW;
            const char* r8p = r0p + 8 * STAGE_ROW;
            #pragma unroll
            for (int kt = 0; kt < 4; kt++) {
                const int cb = (kt * 16 + ql * 2) * 4;
                float2 f0 = *reinterpret_cast<const float2*>(r0p + cb);
                float2 f1 = *reinterpret_cast<const float2*>(r8p + cb);
                float2 f2 = *reinterpret_cast<const float2*>(r0p + cb + 32);
                float2 f3 = *reinterpret_cast<const float2*>(r8p + cb + 32);
                xf[m][kt][0] = pack_bf2(f0.x, f0.y);
                xf[m][kt][1] = pack_bf2(f1.x, f1.y);
                xf[m][kt][2] = pack_bf2(f2.x, f2.y);
                xf[m][kt][3] = pack_bf2(f3.x, f3.y);
            }
        }

        // ---- gates A on tensor core ----
        float4 gAf[2][2];
        uint32_t gA2[4][2][2];
        #pragma unroll
        for (int m = 0; m < 2; m++) {
            float4 gf[2]; uint32_t g2c[4][2];
            gates_from_frags(xf[m], wgA0, wgA1, ql, gf, g2c);
            gAf[m][0] = gf[0]; gAf[m][1] = gf[1];
            #pragma unroll
            for (int e = 0; e < 4; e++) { gA2[e][m][0] = g2c[e][0]; gA2[e][m][1] = g2c[e][1]; }
        }

        // ---- layer A: acc init = -sum_e g_e c_a (bias), then GEMM ----
        float acc[2][8][4];
        #pragma unroll
        for (int n = 0; n < 8; n++) {
            int c = n * 8 + ql * 2;
            float4 c0 = CA4[c], c1 = CA4[c + 1];
            #pragma unroll
            for (int m = 0; m < 2; m++) {
                acc[m][n][0] = -dot4(gAf[m][0], c0);
                acc[m][n][1] = -dot4(gAf[m][0], c1);
                acc[m][n][2] = -dot4(gAf[m][1], c0);
                acc[m][n][3] = -dot4(gAf[m][1], c1);
            }
        }
        run_layer(acc, xf, gA2, sb + SM_W, lane);

        // ---- repack h: C-fragment layout == A-fragment layout (per kt) ----
        #pragma unroll
        for (int m = 0; m < 2; m++)
            #pragma unroll
            for (int kt = 0; kt < 4; kt++) {
                xf[m][kt][0] = pack_bf2(acc[m][2*kt][0],   acc[m][2*kt][1]);
                xf[m][kt][1] = pack_bf2(acc[m][2*kt][2],   acc[m][2*kt][3]);
                xf[m][kt][2] = pack_bf2(acc[m][2*kt+1][0], acc[m][2*kt+1][1]);
                xf[m][kt][3] = pack_bf2(acc[m][2*kt+1][2], acc[m][2*kt+1][3]);
            }

        // ---- gates B on tensor core ----
        float4 gBf[2][2];
        uint32_t gB2[4][2][2];
        #pragma unroll
        for (int m = 0; m < 2; m++) {
            float4 gf[2]; uint32_t g2c[4][2];
            gates_from_frags(xf[m], wgB0, wgB1, ql, gf, g2c);
            gBf[m][0] = gf[0]; gBf[m][1] = gf[1];
            #pragma unroll
            for (int e = 0; e < 4; e++) { gB2[e][m][0] = g2c[e][0]; gB2[e][m][1] = g2c[e][1]; }
        }

        // ---- layer B acc init: x (residual, from stage) - sum_e g_e c_b ----
        #pragma unroll
        for (int n = 0; n < 8; n++) {
            int c = n * 8 + ql * 2;
            float4 c0 = CB4[c], c1 = CB4[c + 1];
            #pragma unroll
            for (int m = 0; m < 2; m++) {
                const char* rlp = stage + (m * 16 + qr) * STAGE_ROW + c * 4;
                float2 xl = *reinterpret_cast<const float2*>(rlp);
                float2 xh = *reinterpret_cast<const float2*>(rlp + 8 * STAGE_ROW);
                acc[m][n][0] = xl.x - dot4(gBf[m][0], c0);
                acc[m][n][1] = xl.y - dot4(gBf[m][0], c1);
                acc[m][n][2] = xh.x - dot4(gBf[m][1], c0);
                acc[m][n][3] = xh.y - dot4(gBf[m][1], c1);
            }
        }

        // ---- stage free: kick off next unit's cp.async, then layer B GEMM --
        __syncwarp();
        if (un < nunits) issue_stage(x, un, stage_u32, lane);

        run_layer(acc, xf, gB2, sb + SM_W + 32768, lane);

        // ---- epilogue: pure streaming stores ----
        #pragma unroll
        for (int m = 0; m < 2; m++) {
            const size_t rl = rowbase + (size_t)(m * 16 + qr);
            const size_t rh = rl + 8;
            #pragma unroll
            for (int n = 0; n < 8; n++) {
                int c = n * 8 + ql * 2;
                __stcs(reinterpret_cast<float2*>(out + rl * 64 + c),
                       make_float2(acc[m][n][0], acc[m][n][1]));
                __stcs(reinterpret_cast<float2*>(out + rh * 64 + c),
                       make_float2(acc[m][n][2], acc[m][n][3]));
            }
        }

        u = un;
    }
}

// ------------------------------- launch -----------------------------------

extern "C" void kernel_launch(void* const* d_in, const int* in_sizes, int n_in,
                              void* d_out, int out_size) {
    const float* x   = (const float*)d_in[0];
    const float* wga = (const float*)d_in[1];
    const float* wea = (const float*)d_in[2];
    const float* bea = (const float*)d_in[3];
    const float* wgb = (const float*)d_in[4];
    const float* web = (const float*)d_in[5];
    const float* beb = (const float*)d_in[6];
    float* out = (float*)d_out;

    const int ntok   = in_sizes[0] / 64;
    const int nunits = ntok / 32;

    prep_kernel<<<64, 512>>>(wea, bea, web, beb);

    cudaFuncSetAttribute(moe_kernel, cudaFuncAttributeMaxDynamicSharedMemorySize, SMEM_TOTAL);
    moe_kernel<<<GRID, 384, SMEM_TOTAL>>>(x, wga, wgb, out, nunits);
}

// round 12
// speedup vs baseline: 2.7651x; 1.1212x over previous
#include <cuda_runtime.h>
#include <cuda_bf16.h>
#include <cstdint>

// ---------------------------------------------------------------------------
// SPMoEAdaptor: out = moe_b(moe_a(x)) + x
//   moe(x) = sum_e softmax(x@Wg)[:,e] * ((x - b_e) @ W_e)
//          = sum_e (g_e * x) @ W_e  -  sum_e g_e * (b_e @ W_e)
// R11: R10 (bf16 HMMA, cp.async x-stage, 384-thr CTA, work-stealing) +
// zero-bias fast path: prep detects c_e = b_e@W_e == 0 (true here: b_exp is
// zeros) and sets g_cflag; main kernel then skips ALL bias-fold dot4s
// (512 fp32 FMA + 64 LDS per unit) and their serial chains. General fold
// path retained for nonzero bias. Output bit-identical when flag set.
// ---------------------------------------------------------------------------

namespace {
// dynamic smem layout (bytes)
constexpr int SM_W    = 0;              // 64KB bf16 weights, both layers (n-major)
constexpr int SM_WGA  = 65536;          // 64 x float4 (w_gate_a as [d][e])
constexpr int SM_WGB  = 66560;
constexpr int SM_CA   = 67584;          // 64 x float4 (c_a as [f][e])
constexpr int SM_CB   = 68608;
constexpr int SM_STAGE = 69632;         // 12 warps x 9216B x-stage
constexpr int STAGE_ROW  = 288;         // 256B data + 32B pad (bank-conflict-free)
constexpr int STAGE_WARP = 32 * STAGE_ROW;   // 9216
constexpr int SMEM_TOTAL = SM_STAGE + 12 * STAGE_WARP;  // 180224

constexpr int GRID = 148;               // 1 CTA per SM
}

// device-global scratch (allocation-free rule)
// n-major: row f (0..63), 256 bf16 per row (k = e*64+d), chunk-XOR swizzled.
__device__ __align__(16) __nv_bfloat16 g_wswz[2][64 * 256];
__device__ __align__(16) float g_c[2][64 * 4];   // c[L][f*4+e] = (b_e @ W_e)[f]
__device__ unsigned g_unit_ctr;                  // work-stealing counter
__device__ int g_cflag;                          // 1 iff all c == 0 (skip folds)

// ------------------------------- helpers ----------------------------------

__device__ __forceinline__ uint32_t smem_u32(const void* p) {
    uint32_t a;
    asm("{ .reg .u64 t; cvta.to.shared.u64 t, %1; cvt.u32.u64 %0, t; }" : "=r"(a) : "l"(p));
    return a;
}

__device__ __forceinline__ void ldsm_x4(uint32_t* r, uint32_t addr) {
    asm volatile("ldmatrix.sync.aligned.m8n8.x4.shared.b16 {%0,%1,%2,%3}, [%4];"
                 : "=r"(r[0]), "=r"(r[1]), "=r"(r[2]), "=r"(r[3]) : "r"(addr));
}

__device__ __forceinline__ void mma_bf16(float* d, const uint32_t* a,
                                         uint32_t b0, uint32_t b1) {
    asm volatile("mma.sync.aligned.m16n8k16.row.col.f32.bf16.bf16.f32 "
                 "{%0,%1,%2,%3}, {%4,%5,%6,%7}, {%8,%9}, {%0,%1,%2,%3};"
                 : "+f"(d[0]), "+f"(d[1]), "+f"(d[2]), "+f"(d[3])
                 : "r"(a[0]), "r"(a[1]), "r"(a[2]), "r"(a[3]), "r"(b0), "r"(b1));
}

__device__ __forceinline__ uint32_t pack_bf2(float lo, float hi) {
    __nv_bfloat162 t = __floats2bfloat162_rn(lo, hi);
    return *reinterpret_cast<uint32_t*>(&t);
}

__device__ __forceinline__ uint32_t bf2bcast(float v) { return pack_bf2(v, v); }

__device__ __forceinline__ uint32_t hmul2u(uint32_t a, uint32_t b) {
    __nv_bfloat162 r = __hmul2(*reinterpret_cast<__nv_bfloat162*>(&a),
                               *reinterpret_cast<__nv_bfloat162*>(&b));
    return *reinterpret_cast<uint32_t*>(&r);
}

__device__ __forceinline__ float dot4(float4 a, float4 b) {
    return a.x * b.x + a.y * b.y + a.z * b.z + a.w * b.w;
}

__device__ __forceinline__ float4 softmax4(float4 l) {
    float mx = fmaxf(fmaxf(l.x, l.y), fmaxf(l.z, l.w));
    float e0 = __expf(l.x - mx), e1 = __expf(l.y - mx),
          e2 = __expf(l.z - mx), e3 = __expf(l.w - mx);
    float inv = 1.f / (e0 + e1 + e2 + e3);
    return make_float4(e0 * inv, e1 * inv, e2 * inv, e3 * inv);
}

__device__ __forceinline__ unsigned steal(int lane) {
    unsigned v = 0;
    if (lane == 0) v = atomicAdd(&g_unit_ctr, 1u);
    return __shfl_sync(0xffffffffu, v, 0);
}

// issue cp.async copies of unit u's 32x64 fp32 x-rows into this warp's stage
__device__ __forceinline__ void issue_stage(const float* __restrict__ x, unsigned u,
                                            uint32_t dstbase, int lane) {
    const float* src = x + (size_t)u * 32 * 64;
    const int hl = lane >> 4;      // 0/1
    const int ch = lane & 15;      // 16B chunk within row
    #pragma unroll
    for (int i = 0; i < 16; i++) {
        int row = 2 * i + hl;
        uint32_t dst = dstbase + (uint32_t)(row * STAGE_ROW + ch * 16);
        const float* s = src + row * 64 + ch * 4;
        asm volatile("cp.async.cg.shared.global [%0], [%1], 16;" :: "r"(dst), "l"(s));
    }
    asm volatile("cp.async.commit_group;" ::: "memory");
}

__device__ __forceinline__ void stage_wait() {
    asm volatile("cp.async.wait_group 0;" ::: "memory");
    __syncwarp();
}

// one MoE GEMM layer: acc[2][8][4] += sum over e,kt of (g_e o A_frag) @ W_frag
__device__ __forceinline__ void run_layer(float acc[2][8][4],
                                          const uint32_t xf[2][4][4],
                                          const uint32_t g2[4][2][2],
                                          uint32_t wbase, int lane) {
    const int l7 = lane & 7;
    const uint32_t lane_row = (uint32_t)(((lane >> 4) & 1) * 8 + l7);
    const uint32_t kh = (uint32_t)((lane >> 3) & 1);
    const uint32_t lane_base = wbase + lane_row * 512u;
    #pragma unroll
    for (int e = 0; e < 4; e++) {
        #pragma unroll
        for (int kt = 0; kt < 4; kt++) {
            uint32_t a[2][4];
            #pragma unroll
            for (int m = 0; m < 2; m++) {
                a[m][0] = hmul2u(xf[m][kt][0], g2[e][m][0]);
                a[m][1] = hmul2u(xf[m][kt][1], g2[e][m][1]);
                a[m][2] = hmul2u(xf[m][kt][2], g2[e][m][0]);
                a[m][3] = hmul2u(xf[m][kt][3], g2[e][m][1]);
            }
            const uint32_t c0 = (uint32_t)(e * 8 + kt * 2) + kh;
            const uint32_t coff = ((c0 ^ (uint32_t)l7) << 4);
            #pragma unroll
            for (int np = 0; np < 4; np++) {
                uint32_t b[4];
                ldsm_x4(b, lane_base + (uint32_t)np * 8192u + coff);
                #pragma unroll
                for (int m = 0; m < 2; m++) {
                    mma_bf16(acc[m][2 * np],     a[m], b[0], b[1]);
                    mma_bf16(acc[m][2 * np + 1], a[m], b[2], b[3]);
                }
            }
        }
    }
}

// gates from A-fragments via tensor core (cols 4..7 duplicate experts 0..3;
// one shfl_xor(1) completes the gather). Two accumulator chains.
__device__ __forceinline__ void gates_from_frags(const uint32_t xf[4][4],
                                                 const uint32_t* wg0,
                                                 const uint32_t* wg1,
                                                 int ql,
                                                 float4 gf[2],
                                                 uint32_t g2[4][2]) {
    float l[4]  = {0.f, 0.f, 0.f, 0.f};
    float l2[4] = {0.f, 0.f, 0.f, 0.f};
    mma_bf16(l,  xf[0], wg0[0], wg1[0]);
    mma_bf16(l2, xf[1], wg0[1], wg1[1]);
    mma_bf16(l,  xf[2], wg0[2], wg1[2]);
    mma_bf16(l2, xf[3], wg0[3], wg1[3]);
    l[0] += l2[0]; l[1] += l2[1]; l[2] += l2[2]; l[3] += l2[3];
    float r0 = __shfl_xor_sync(0xffffffffu, l[0], 1);
    float r1 = __shfl_xor_sync(0xffffffffu, l[1], 1);
    float r2 = __shfl_xor_sync(0xffffffffu, l[2], 1);
    float r3 = __shfl_xor_sync(0xffffffffu, l[3], 1);
    bool even = (ql & 1) == 0;
    float4 La = even ? make_float4(l[0], l[1], r0, r1)
                     : make_float4(r0, r1, l[0], l[1]);
    float4 Lb = even ? make_float4(l[2], l[3], r2, r3)
                     : make_float4(r2, r3, l[2], l[3]);
    float4 ga = softmax4(La);
    float4 gb = softmax4(Lb);
    gf[0] = ga; gf[1] = gb;
    g2[0][0] = bf2bcast(ga.x); g2[1][0] = bf2bcast(ga.y);
    g2[2][0] = bf2bcast(ga.z); g2[3][0] = bf2bcast(ga.w);
    g2[0][1] = bf2bcast(gb.x); g2[1][1] = bf2bcast(gb.y);
    g2[2][1] = bf2bcast(gb.z); g2[3][1] = bf2bcast(gb.w);
}

// ------------------------------- prep kernel ------------------------------

__global__ void prep_kernel(const float* __restrict__ wea, const float* __restrict__ bea,
                            const float* __restrict__ web, const float* __restrict__ beb) {
    int idx = blockIdx.x * blockDim.x + threadIdx.x;
    if (idx == 0) { g_unit_ctr = 0; g_cflag = 1; }
    if (idx < 2 * 4 * 64 * 64) {
        int L = idx >> 14;
        int r = idx & 16383;
        int e = r >> 12;
        int d = (r >> 6) & 63;
        int f = r & 63;
        const float* w = L ? web : wea;
        float v = w[(e * 64 + d) * 64 + f];
        int chunk = (e * 8 + (d >> 3)) ^ (f & 7);
        g_wswz[L][f * 256 + chunk * 8 + (d & 7)] = __float2bfloat16(v);
    }
    if (idx < 2 * 4 * 64) {
        int L = idx >> 8;
        int e = (idx >> 6) & 3;
        int f = idx & 63;
        const float* w = L ? web : wea;
        const float* b = L ? beb : bea;
        float s = 0.f;
        for (int d = 0; d < 64; d++)
            s += b[e * 64 + d] * w[(e * 64 + d) * 64 + f];
        g_c[L][f * 4 + e] = s;
        if (s != 0.f) atomicExch(&g_cflag, 0);   // any nonzero bias term -> general path
    }
}

// ------------------------------- main kernel ------------------------------

__global__ void __launch_bounds__(384, 1)
moe_kernel(const float* __restrict__ x,
           const float* __restrict__ wg_a,
           const float* __restrict__ wg_b,
           float* __restrict__ out,
           int nunits_i) {
    extern __shared__ char smem[];
    const uint32_t sb = smem_u32(smem);
    const int tid  = threadIdx.x;
    const int lane = tid & 31;
    const int warp = tid >> 5;          // 0..11
    const unsigned nunits = (unsigned)nunits_i;

    // ---- one-time cooperative weight copies ----
    {
        const uint4* s0 = reinterpret_cast<const uint4*>(g_wswz);
        uint4* dW = reinterpret_cast<uint4*>(smem + SM_W);
        for (int i = tid; i < 4096; i += 384) dW[i] = s0[i];
        float* wga_s = reinterpret_cast<float*>(smem + SM_WGA);
        float* wgb_s = reinterpret_cast<float*>(smem + SM_WGB);
        float* ca_s  = reinterpret_cast<float*>(smem + SM_CA);
        float* cb_s  = reinterpret_cast<float*>(smem + SM_CB);
        if (tid < 256) {
            wga_s[tid] = wg_a[tid]; wgb_s[tid] = wg_b[tid];
            ca_s[tid]  = g_c[0][tid]; cb_s[tid] = g_c[1][tid];
        }
    }
    const bool nofold = (g_cflag != 0);   // uniform; bias terms all zero -> skip folds
    __syncthreads();

    const float4* CA4 = reinterpret_cast<const float4*>(smem + SM_CA);
    const float4* CB4 = reinterpret_cast<const float4*>(smem + SM_CB);

    const int ql = lane & 3;
    const int qr = lane >> 2;
    const char* stage = smem + SM_STAGE + warp * STAGE_WARP;
    const uint32_t stage_u32 = sb + (uint32_t)(SM_STAGE + warp * STAGE_WARP);

    // ---- register-resident Wg B-fragments (tile-invariant) ----
    uint32_t wgA0[4], wgA1[4], wgB0[4], wgB1[4];
    {
        const float* WGAf = reinterpret_cast<const float*>(smem + SM_WGA);
        const float* WGBf = reinterpret_cast<const float*>(smem + SM_WGB);
        const int e4 = qr & 3;
        #pragma unroll
        for (int kt = 0; kt < 4; kt++) {
            int d0 = kt * 16 + 2 * ql;
            wgA0[kt] = pack_bf2(WGAf[d0 * 4 + e4],       WGAf[(d0 + 1) * 4 + e4]);
            wgA1[kt] = pack_bf2(WGAf[(d0 + 8) * 4 + e4], WGAf[(d0 + 9) * 4 + e4]);
            wgB0[kt] = pack_bf2(WGBf[d0 * 4 + e4],       WGBf[(d0 + 1) * 4 + e4]);
            wgB1[kt] = pack_bf2(WGBf[(d0 + 8) * 4 + e4], WGBf[(d0 + 9) * 4 + e4]);
        }
    }

    // ---- work-stealing loop with cp.async staged x ----
    unsigned u = steal(lane);
    if (u < nunits) issue_stage(x, u, stage_u32, lane);

    while (u < nunits) {
        unsigned un = steal(lane);      // pipelined next-unit fetch
        const size_t rowbase = (size_t)u * 32;

        stage_wait();                   // x for unit u ready in smem

        // ---- X fragments from stage (LDS) ----
        uint32_t xf[2][4][4];
        #pragma unroll
        for (int m = 0; m < 2; m++) {
            const char* r0p = stage + (m * 16 + qr) * STAGE_ROW;
            const char* r8p = r0p + 8 * STAGE_ROW;
            #pragma unroll
            for (int kt = 0; kt < 4; kt++) {
                const int cb = (kt * 16 + ql * 2) * 4;
                float2 f0 = *reinterpret_cast<const float2*>(r0p + cb);
                float2 f1 = *reinterpret_cast<const float2*>(r8p + cb);
                float2 f2 = *reinterpret_cast<const float2*>(r0p + cb + 32);
                float2 f3 = *reinterpret_cast<const float2*>(r8p + cb + 32);
                xf[m][kt][0] = pack_bf2(f0.x, f0.y);
                xf[m][kt][1] = pack_bf2(f1.x, f1.y);
                xf[m][kt][2] = pack_bf2(f2.x, f2.y);
                xf[m][kt][3] = pack_bf2(f3.x, f3.y);
            }
        }

        // ---- gates A on tensor core ----
        float4 gAf[2][2];
        uint32_t gA2[4][2][2];
        #pragma unroll
        for (int m = 0; m < 2; m++) {
            float4 gf[2]; uint32_t g2c[4][2];
            gates_from_frags(xf[m], wgA0, wgA1, ql, gf, g2c);
            gAf[m][0] = gf[0]; gAf[m][1] = gf[1];
            #pragma unroll
            for (int e = 0; e < 4; e++) { gA2[e][m][0] = g2c[e][0]; gA2[e][m][1] = g2c[e][1]; }
        }

        // ---- layer A acc init: zero (fast path) or -sum_e g_e c_a ----
        float acc[2][8][4];
        if (nofold) {
            #pragma unroll
            for (int n = 0; n < 8; n++)
                #pragma unroll
                for (int m = 0; m < 2; m++) {
                    acc[m][n][0] = 0.f; acc[m][n][1] = 0.f;
                    acc[m][n][2] = 0.f; acc[m][n][3] = 0.f;
                }
        } else {
            #pragma unroll
            for (int n = 0; n < 8; n++) {
                int c = n * 8 + ql * 2;
                float4 c0 = CA4[c], c1 = CA4[c + 1];
                #pragma unroll
                for (int m = 0; m < 2; m++) {
                    acc[m][n][0] = -dot4(gAf[m][0], c0);
                    acc[m][n][1] = -dot4(gAf[m][0], c1);
                    acc[m][n][2] = -dot4(gAf[m][1], c0);
                    acc[m][n][3] = -dot4(gAf[m][1], c1);
                }
            }
        }
        run_layer(acc, xf, gA2, sb + SM_W, lane);

        // ---- repack h: C-fragment layout == A-fragment layout (per kt) ----
        #pragma unroll
        for (int m = 0; m < 2; m++)
            #pragma unroll
            for (int kt = 0; kt < 4; kt++) {
                xf[m][kt][0] = pack_bf2(acc[m][2*kt][0],   acc[m][2*kt][1]);
                xf[m][kt][1] = pack_bf2(acc[m][2*kt][2],   acc[m][2*kt][3]);
                xf[m][kt][2] = pack_bf2(acc[m][2*kt+1][0], acc[m][2*kt+1][1]);
                xf[m][kt][3] = pack_bf2(acc[m][2*kt+1][2], acc[m][2*kt+1][3]);
            }

        // ---- gates B on tensor core ----
        float4 gBf[2][2];
        uint32_t gB2[4][2][2];
        #pragma unroll
        for (int m = 0; m < 2; m++) {
            float4 gf[2]; uint32_t g2c[4][2];
            gates_from_frags(xf[m], wgB0, wgB1, ql, gf, g2c);
            gBf[m][0] = gf[0]; gBf[m][1] = gf[1];
            #pragma unroll
            for (int e = 0; e < 4; e++) { gB2[e][m][0] = g2c[e][0]; gB2[e][m][1] = g2c[e][1]; }
        }

        // ---- layer B acc init: residual (fast path) or residual - fold ----
        if (nofold) {
            #pragma unroll
            for (int n = 0; n < 8; n++) {
                int c = n * 8 + ql * 2;
                #pragma unroll
                for (int m = 0; m < 2; m++) {
                    const char* rlp = stage + (m * 16 + qr) * STAGE_ROW + c * 4;
                    float2 xl = *reinterpret_cast<const float2*>(rlp);
                    float2 xh = *reinterpret_cast<const float2*>(rlp + 8 * STAGE_ROW);
                    acc[m][n][0] = xl.x; acc[m][n][1] = xl.y;
                    acc[m][n][2] = xh.x; acc[m][n][3] = xh.y;
                }
            }
        } else {
            #pragma unroll
            for (int n = 0; n < 8; n++) {
                int c = n * 8 + ql * 2;
                float4 c0 = CB4[c], c1 = CB4[c + 1];
                #pragma unroll
                for (int m = 0; m < 2; m++) {
                    const char* rlp = stage + (m * 16 + qr) * STAGE_ROW + c * 4;
                    float2 xl = *reinterpret_cast<const float2*>(rlp);
                    float2 xh = *reinterpret_cast<const float2*>(rlp + 8 * STAGE_ROW);
                    acc[m][n][0] = xl.x - dot4(gBf[m][0], c0);
                    acc[m][n][1] = xl.y - dot4(gBf[m][0], c1);
                    acc[m][n][2] = xh.x - dot4(gBf[m][1], c0);
                    acc[m][n][3] = xh.y - dot4(gBf[m][1], c1);
                }
            }
        }

        // ---- stage free: kick off next unit's cp.async, then layer B GEMM --
        __syncwarp();
        if (un < nunits) issue_stage(x, un, stage_u32, lane);

        run_layer(acc, xf, gB2, sb + SM_W + 32768, lane);

        // ---- epilogue: pure streaming stores ----
        #pragma unroll
        for (int m = 0; m < 2; m++) {
            const size_t rl = rowbase + (size_t)(m * 16 + qr);
            const size_t rh = rl + 8;
            #pragma unroll
            for (int n = 0; n < 8; n++) {
                int c = n * 8 + ql * 2;
                __stcs(reinterpret_cast<float2*>(out + rl * 64 + c),
                       make_float2(acc[m][n][0], acc[m][n][1]));
                __stcs(reinterpret_cast<float2*>(out + rh * 64 + c),
                       make_float2(acc[m][n][2], acc[m][n][3]));
            }
        }

        u = un;
    }
}

// ------------------------------- launch -----------------------------------

extern "C" void kernel_launch(void* const* d_in, const int* in_sizes, int n_in,
                              void* d_out, int out_size) {
    const float* x   = (const float*)d_in[0];
    const float* wga = (const float*)d_in[1];
    const float* wea = (const float*)d_in[2];
    const float* bea = (const float*)d_in[3];
    const float* wgb = (const float*)d_in[4];
    const float* web = (const float*)d_in[5];
    const float* beb = (const float*)d_in[6];
    float* out = (float*)d_out;

    const int ntok   = in_sizes[0] / 64;
    const int nunits = ntok / 32;

    prep_kernel<<<64, 512>>>(wea, bea, web, beb);

    cudaFuncSetAttribute(moe_kernel, cudaFuncAttributeMaxDynamicSharedMemorySize, SMEM_TOTAL);
    moe_kernel<<<GRID, 384, SMEM_TOTAL>>>(x, wga, wgb, out, nunits);
}